// round 14
// baseline (speedup 1.0000x reference)
#include <cuda_runtime.h>
#include <cuda_fp16.h>
#include <cstdint>

#define NT 512

// ---- shared-memory word offsets ----
#define OFF_WF    0        // W quads: 48 groups * 132 = 6336 words
#define OFF_X2P   6336     // x2 packed pairs: 72 rows * stride 37 = 2664
#define OFF_X1P   9000     // x1 packed pairs: 36 rows * 18 = 648
#define OFF_P0    9648     // x0 pair (x[c],x[c+1]): 18*18 = 324
#define OFF_P0B   9972     // x0 pair (x[c],0):      18*18 = 324
#define OFF_X0F   10296    // x0 fp32 (for xsel):    18*18 = 324
#define SMW_TOTAL 10620    // 42480 bytes -> 2 CTAs/SM

#define X2STR 37           // padded: A-load banks 5t+2g -> max 2-way conflicts

__device__ __align__(16) uint32_t g_wfrag[48 * 132];

// K-step/slot -> original weight row (kk in [0,189)), or -1 = zero pad.
// Must mirror the A-side address scheme in the mainloop exactly.
__host__ __device__ __forceinline__ void tapmap(int s, int reg, int t,
                                                int& lo, int& hi)
{
    if (s < 6)       { int di = reg ? 4 + t : t;                // layer2 rows 0..7
                       lo = 45 + 12 * di + 2 * s; hi = lo + 1; }
    else if (s < 9)  { int m = s - 6; int di = 8 + t;           // layer2 rows 8..11
                       int jj = 2 * m + reg;
                       lo = 45 + 12 * di + 2 * jj; hi = lo + 1; }
    else if (s == 9) { int di = t;                              // layer1 rows 0..3, dj 0..3
                       lo = 9 + 6 * di + 2 * reg; hi = lo + 1; }
    else if (s == 10) {
        if (reg == 0) { lo = 9 + 6 * t + 4; hi = lo + 1; }      // layer1 rows 0..3, dj 4,5
        else { int di = 4 + (t & 1); int jj = t >> 1;           // layer1 rows 4,5, dj 0..3
               lo = 9 + 6 * di + 2 * jj; hi = lo + 1; }
    } else { // s == 11
        if (reg == 0) {
            if (t < 2) { lo = 9 + 6 * (4 + t) + 4; hi = lo + 1; }  // layer1 r4,5 dj4,5
            else       { lo = 3 * (t - 2); hi = lo + 1; }          // layer0 r0,1 dj0,1
        } else {
            if (t == 0) { lo = 6; hi = 7; }                        // layer0 r2 dj0,1
            else        { lo = 3 * (t - 1) + 2; hi = -1; }         // layer0 dj2 (+zero)
        }
    }
}

static __host__ __device__ __forceinline__ uint32_t packh2f(float lo, float hi)
{
    __half2 h = __floats2half2_rn(lo, hi);
    return *reinterpret_cast<uint32_t*>(&h);
}

// Group Q = s*4 + nbp covers n-blocks 2*nbp, 2*nbp+1. Word layout inside group:
// off(slot=8t+g, c) = 16*g + 4*t + c; LDS.128 at (16g+4t) is conflict-free.
__global__ void wprep(const float* __restrict__ gw)
{
    int i = blockIdx.x * 256 + threadIdx.x;
    if (i >= 1536) return;
    int Q = i >> 5, slot = i & 31;
    int t = slot >> 3, g = slot & 7;
    int s = Q >> 2, nbp = Q & 3;
    int lo0, hi0, lo1, hi1;
    tapmap(s, 0, t, lo0, hi0);
    tapmap(s, 1, t, lo1, hi1);
    int nn0 = (2 * nbp) * 8 + g;
    int nn1 = nn0 + 8;
    auto rd = [&](int kk, int nn) -> float {
        return (kk >= 0) ? gw[kk * 64 + nn] : 0.0f;
    };
    uint4 val;
    val.x = packh2f(rd(lo0, nn0), rd(hi0, nn0));
    val.y = packh2f(rd(lo1, nn0), rd(hi1, nn0));
    val.z = packh2f(rd(lo0, nn1), rd(hi0, nn1));
    val.w = packh2f(rd(lo1, nn1), rd(hi1, nn1));
    *reinterpret_cast<uint4*>(g_wfrag + Q * 132 + 16 * g + 4 * t) = val;
}

static __device__ __forceinline__ void mma_f16(float* c,
                                               uint32_t a0, uint32_t a1,
                                               uint32_t a2, uint32_t a3,
                                               uint32_t b0, uint32_t b1)
{
    asm volatile(
        "mma.sync.aligned.m16n8k16.row.col.f32.f16.f16.f32 "
        "{%0,%1,%2,%3}, {%4,%5,%6,%7}, {%8,%9}, {%0,%1,%2,%3};"
        : "+f"(c[0]), "+f"(c[1]), "+f"(c[2]), "+f"(c[3])
        : "r"(a0), "r"(a1), "r"(a2), "r"(a3), "r"(b0), "r"(b1));
}

// ---------------------------------------------------------------------------
// CTA: batch n, 16x16 tile of positions, 512 threads. Warp w = tile row w.
// ---------------------------------------------------------------------------
__global__ void __launch_bounds__(NT, 2)
sr_f16(const float* __restrict__ gx0, const float* __restrict__ gx1,
       const float* __restrict__ gx2, float* __restrict__ out)
{
    __shared__ __align__(16) uint32_t smw[SMW_TOTAL];

    const int tid  = threadIdx.x;
    const int wid  = tid >> 5;
    const int lane = tid & 31;
    const int n    = blockIdx.z;
    const int i0   = blockIdx.y * 16;
    const int j0   = blockIdx.x * 16;

    // ---- stage W fragment quads (vector copy) ----
    {
        const uint4* src = (const uint4*)g_wfrag;
        uint4* dst = (uint4*)(smw + OFF_WF);
        for (int i = tid; i < 1584; i += NT) dst[i] = src[i];
    }
    // ---- stage x2 as packed half pairs (row stride X2STR, 72 rows) ----
    {
        const float* src = gx2 + n * 65536;
        for (int i = tid; i < 2592; i += NT) {
            int row = i / 36, pc = i - row * 36;
            int gi = 4 * i0 - 4 + row;
            int gj = 4 * j0 - 4 + 2 * pc;            // always even
            float2 v = make_float2(0.0f, 0.0f);
            if ((unsigned)gi < 256u && (unsigned)gj < 256u)
                v = *(const float2*)(src + gi * 256 + gj);
            smw[OFF_X2P + row * X2STR + pc] = packh2f(v.x, v.y);
        }
    }
    // ---- stage x1 pairs ----
    {
        const float* src = gx1 + n * 16384;
        for (int i = tid; i < 648; i += NT) {
            int row = i / 18, pc = i - row * 18;
            int gi = 2 * i0 - 2 + row;
            int gj = 2 * j0 - 2 + 2 * pc;            // always even
            float2 v = make_float2(0.0f, 0.0f);
            if ((unsigned)gi < 128u && (unsigned)gj < 128u)
                v = *(const float2*)(src + gi * 128 + gj);
            smw[OFF_X1P + i] = packh2f(v.x, v.y);
        }
    }
    // ---- stage x0: fp32 (xsel) + two pair variants, 18x18 ----
    {
        const float* src = gx0 + n * 4096;
        for (int i = tid; i < 324; i += NT) {
            int row = i / 18, col = i - row * 18;
            int gi = i0 - 1 + row, gj = j0 - 1 + col;
            float a = 0.0f, b = 0.0f;
            if ((unsigned)gi < 64u) {
                const float* rp = src + gi * 64;
                if ((unsigned)gj < 64u)       a = rp[gj];
                if ((unsigned)(gj + 1) < 64u) b = rp[gj + 1];
            }
            smw[OFF_X0F + i] = __float_as_uint(a);
            smw[OFF_P0  + i] = packh2f(a, b);
            smw[OFF_P0B + i] = packh2f(a, 0.0f);
        }
    }
    __syncthreads();

    // ---- per-thread precomputed bases ----
    const int g = lane >> 2, t = lane & 3;
    const int r = wid;                    // tile row for this warp (0..15)
    const int i2   = OFF_X2P + (4 * r + t) * X2STR + 2 * g;
    const int i1   = OFF_X1P + (2 * r + t) * 18 + g;
    const int u1o  = OFF_X1P + 2 * r * 18 + g + 72 + (t & 1) * 18 + (t >> 1);
    const int s11a = (t < 2) ? (OFF_X1P + (2 * r + 4 + t) * 18 + g + 2)
                             : (OFF_P0  + (r + t - 2) * 18 + g);
    const int s11b = (t == 0) ? (OFF_P0  + (r + 2) * 18 + g)
                              : (OFF_P0B + (r + t - 1) * 18 + g + 2);
    const int wfb  = OFF_WF + 16 * g + 4 * t;

    float acc[8][4];
#pragma unroll
    for (int nb = 0; nb < 8; ++nb)
#pragma unroll
        for (int q = 0; q < 4; ++q) acc[nb][q] = 0.0f;

#pragma unroll
    for (int s = 0; s < 12; ++s) {
        // -- all loads of this k-step first (A quad + 4 B quads) --
        uint32_t a0, a1, a2, a3;
        if (s < 6) {
            // a2/a3 are +4 patch rows = +4*X2STR = +148
            a0 = smw[i2 + s];        a1 = smw[i2 + 16 + s];
            a2 = smw[i2 + 148 + s];  a3 = smw[i2 + 164 + s];
        } else if (s < 9) {
            // +8 patch rows = +8*X2STR = +296
            const int m2 = 2 * (s - 6);
            a0 = smw[i2 + 296 + m2]; a1 = smw[i2 + 312 + m2];
            a2 = smw[i2 + 297 + m2]; a3 = smw[i2 + 313 + m2];
        } else if (s == 9) {
            a0 = smw[i1];     a1 = smw[i1 + 8];
            a2 = smw[i1 + 1]; a3 = smw[i1 + 9];
        } else if (s == 10) {
            a0 = smw[i1 + 2]; a1 = smw[i1 + 10];
            a2 = smw[u1o];    a3 = smw[u1o + 8];
        } else {
            a0 = smw[s11a];   a1 = smw[s11a + 8];
            a2 = smw[s11b];   a3 = smw[s11b + 8];
        }
        uint4 b0 = *(const uint4*)(smw + wfb + (s * 4 + 0) * 132);
        uint4 b1 = *(const uint4*)(smw + wfb + (s * 4 + 1) * 132);
        uint4 b2 = *(const uint4*)(smw + wfb + (s * 4 + 2) * 132);
        uint4 b3 = *(const uint4*)(smw + wfb + (s * 4 + 3) * 132);

        mma_f16(acc[0], a0, a1, a2, a3, b0.x, b0.y);
        mma_f16(acc[1], a0, a1, a2, a3, b0.z, b0.w);
        mma_f16(acc[2], a0, a1, a2, a3, b1.x, b1.y);
        mma_f16(acc[3], a0, a1, a2, a3, b1.z, b1.w);
        mma_f16(acc[4], a0, a1, a2, a3, b2.x, b2.y);
        mma_f16(acc[5], a0, a1, a2, a3, b2.z, b2.w);
        mma_f16(acc[6], a0, a1, a2, a3, b3.x, b3.y);
        mma_f16(acc[7], a0, a1, a2, a3, b3.z, b3.w);
    }

    // ---- epilogue: positions (r, g) and (r, g+8) ----
    // Logits tiny (|x| < ~1): softmax without max-subtraction is safe;
    // exp(relu(x)) == fmax(exp(x), 1).
#pragma unroll
    for (int rr = 0; rr < 2; ++rr) {
        const int c = g + 8 * rr;
        const float xsel = __uint_as_float(smw[OFF_X0F + (r + 1) * 18 + (c + 1)]);

        float e[16];
#pragma unroll
        for (int nb = 0; nb < 8; ++nb) {
            e[2 * nb]     = fmaxf(__expf(acc[nb][rr * 2]),     1.0f);
            e[2 * nb + 1] = fmaxf(__expf(acc[nb][rr * 2 + 1]), 1.0f);
        }
        float sum[8];
#pragma unroll
        for (int o = 0; o < 8; ++o) sum[o] = e[o] + e[o + 8];
#pragma unroll
        for (int o = 0; o < 4; ++o) sum[o] += sum[o + 4];
        float ssum = (sum[0] + sum[1]) + (sum[2] + sum[3]);
        ssum += __shfl_xor_sync(0xffffffffu, ssum, 1);
        ssum += __shfl_xor_sync(0xffffffffu, ssum, 2);

        const float scale = __fdividef(xsel, ssum);

        const int gi = i0 + r, gj = j0 + c;
        float* base = out + ((size_t)n << 18) + (size_t)(gi * 8) * 512
                          + gj * 8 + 2 * t;
#pragma unroll
        for (int nb = 0; nb < 8; ++nb) {
            float2 o2 = make_float2(scale * e[2 * nb], scale * e[2 * nb + 1]);
            *(float2*)(base + (size_t)nb * 512) = o2;
        }
    }
}

extern "C" void kernel_launch(void* const* d_in, const int* in_sizes, int n_in,
                              void* d_out, int out_size)
{
    const float* x0 = (const float*)d_in[0];
    const float* x1 = (const float*)d_in[1];
    const float* x2 = (const float*)d_in[2];
    const float* w  = (const float*)d_in[3];
    float* out = (float*)d_out;

    wprep<<<6, 256>>>(w);
    dim3 grid(4, 4, 64);   // 1024 CTAs
    sr_f16<<<grid, NT>>>(x0, x1, x2, out);
}

// round 15
// speedup vs baseline: 1.4069x; 1.4069x over previous
#include <cuda_runtime.h>
#include <cuda_fp16.h>
#include <cstdint>

#define NT 512

// ---- shared-memory word offsets ----
#define OFF_WF    0        // W quads: 48 groups * 132 = 6336 words
#define OFF_X2P   6336     // x2 packed pairs: 72 rows * stride 37 = 2664
#define OFF_X1P   9000     // x1 packed pairs: 36 rows * 18 = 648
#define OFF_P0    9648     // x0 pair (x[c],x[c+1]): 18*18 = 324
#define OFF_P0B   9972     // x0 pair (x[c],0):      18*18 = 324
#define OFF_X0F   10296    // x0 fp32 (for xsel):    18*18 = 324
#define SMW_TOTAL 10620    // 42480 bytes -> 2 CTAs/SM

#define X2STR 37           // padded: A-load banks 5t+2g -> max 2-way conflicts

__device__ __align__(16) uint32_t g_wfrag[48 * 132];

// K-step/slot -> original weight row (kk in [0,189)), or -1 = zero pad.
// Must mirror the A-side address scheme in the mainloop exactly.
__host__ __device__ __forceinline__ void tapmap(int s, int reg, int t,
                                                int& lo, int& hi)
{
    if (s < 6)       { int di = reg ? 4 + t : t;                // layer2 rows 0..7
                       lo = 45 + 12 * di + 2 * s; hi = lo + 1; }
    else if (s < 9)  { int m = s - 6; int di = 8 + t;           // layer2 rows 8..11
                       int jj = 2 * m + reg;
                       lo = 45 + 12 * di + 2 * jj; hi = lo + 1; }
    else if (s == 9) { int di = t;                              // layer1 rows 0..3, dj 0..3
                       lo = 9 + 6 * di + 2 * reg; hi = lo + 1; }
    else if (s == 10) {
        if (reg == 0) { lo = 9 + 6 * t + 4; hi = lo + 1; }      // layer1 rows 0..3, dj 4,5
        else { int di = 4 + (t & 1); int jj = t >> 1;           // layer1 rows 4,5, dj 0..3
               lo = 9 + 6 * di + 2 * jj; hi = lo + 1; }
    } else { // s == 11
        if (reg == 0) {
            if (t < 2) { lo = 9 + 6 * (4 + t) + 4; hi = lo + 1; }  // layer1 r4,5 dj4,5
            else       { lo = 3 * (t - 2); hi = lo + 1; }          // layer0 r0,1 dj0,1
        } else {
            if (t == 0) { lo = 6; hi = 7; }                        // layer0 r2 dj0,1
            else        { lo = 3 * (t - 1) + 2; hi = -1; }         // layer0 dj2 (+zero)
        }
    }
}

static __host__ __device__ __forceinline__ uint32_t packh2f(float lo, float hi)
{
    __half2 h = __floats2half2_rn(lo, hi);
    return *reinterpret_cast<uint32_t*>(&h);
}

// Group Q = s*4 + nbp covers n-blocks 2*nbp, 2*nbp+1. Word layout inside group:
// off(slot=8t+g, c) = 16*g + 4*t + c; LDS.128 at (16g+4t) is conflict-free.
__global__ void wprep(const float* __restrict__ gw)
{
    int i = blockIdx.x * 256 + threadIdx.x;
    if (i >= 1536) return;
    int Q = i >> 5, slot = i & 31;
    int t = slot >> 3, g = slot & 7;
    int s = Q >> 2, nbp = Q & 3;
    int lo0, hi0, lo1, hi1;
    tapmap(s, 0, t, lo0, hi0);
    tapmap(s, 1, t, lo1, hi1);
    int nn0 = (2 * nbp) * 8 + g;
    int nn1 = nn0 + 8;
    auto rd = [&](int kk, int nn) -> float {
        return (kk >= 0) ? gw[kk * 64 + nn] : 0.0f;
    };
    uint4 val;
    val.x = packh2f(rd(lo0, nn0), rd(hi0, nn0));
    val.y = packh2f(rd(lo1, nn0), rd(hi1, nn0));
    val.z = packh2f(rd(lo0, nn1), rd(hi0, nn1));
    val.w = packh2f(rd(lo1, nn1), rd(hi1, nn1));
    *reinterpret_cast<uint4*>(g_wfrag + Q * 132 + 16 * g + 4 * t) = val;
}

static __device__ __forceinline__ void mma_f16(float* c,
                                               uint32_t a0, uint32_t a1,
                                               uint32_t a2, uint32_t a3,
                                               uint32_t b0, uint32_t b1)
{
    asm volatile(
        "mma.sync.aligned.m16n8k16.row.col.f32.f16.f16.f32 "
        "{%0,%1,%2,%3}, {%4,%5,%6,%7}, {%8,%9}, {%0,%1,%2,%3};"
        : "+f"(c[0]), "+f"(c[1]), "+f"(c[2]), "+f"(c[3])
        : "r"(a0), "r"(a1), "r"(a2), "r"(a3), "r"(b0), "r"(b1));
}

// ---------------------------------------------------------------------------
// CTA: batch n, 16x16 tile of positions, 512 threads. Warp w = tile row w.
// ---------------------------------------------------------------------------
__global__ void __launch_bounds__(NT, 2)
sr_f16(const float* __restrict__ gx0, const float* __restrict__ gx1,
       const float* __restrict__ gx2, float* __restrict__ out)
{
    __shared__ __align__(16) uint32_t smw[SMW_TOTAL];

    const int tid  = threadIdx.x;
    const int wid  = tid >> 5;
    const int lane = tid & 31;
    const int n    = blockIdx.z;
    const int i0   = blockIdx.y * 16;
    const int j0   = blockIdx.x * 16;

    // ---- stage W fragment quads (vector copy) ----
    {
        const uint4* src = (const uint4*)g_wfrag;
        uint4* dst = (uint4*)(smw + OFF_WF);
        for (int i = tid; i < 1584; i += NT) dst[i] = src[i];
    }
    // ---- stage x2 as packed half pairs (row stride X2STR, 72 rows) ----
    {
        const float* src = gx2 + n * 65536;
        for (int i = tid; i < 2592; i += NT) {
            int row = i / 36, pc = i - row * 36;
            int gi = 4 * i0 - 4 + row;
            int gj = 4 * j0 - 4 + 2 * pc;            // always even
            float2 v = make_float2(0.0f, 0.0f);
            if ((unsigned)gi < 256u && (unsigned)gj < 256u)
                v = *(const float2*)(src + gi * 256 + gj);
            smw[OFF_X2P + row * X2STR + pc] = packh2f(v.x, v.y);
        }
    }
    // ---- stage x1 pairs ----
    {
        const float* src = gx1 + n * 16384;
        for (int i = tid; i < 648; i += NT) {
            int row = i / 18, pc = i - row * 18;
            int gi = 2 * i0 - 2 + row;
            int gj = 2 * j0 - 2 + 2 * pc;            // always even
            float2 v = make_float2(0.0f, 0.0f);
            if ((unsigned)gi < 128u && (unsigned)gj < 128u)
                v = *(const float2*)(src + gi * 128 + gj);
            smw[OFF_X1P + i] = packh2f(v.x, v.y);
        }
    }
    // ---- stage x0: fp32 (xsel) + two pair variants, 18x18 ----
    {
        const float* src = gx0 + n * 4096;
        for (int i = tid; i < 324; i += NT) {
            int row = i / 18, col = i - row * 18;
            int gi = i0 - 1 + row, gj = j0 - 1 + col;
            float a = 0.0f, b = 0.0f;
            if ((unsigned)gi < 64u) {
                const float* rp = src + gi * 64;
                if ((unsigned)gj < 64u)       a = rp[gj];
                if ((unsigned)(gj + 1) < 64u) b = rp[gj + 1];
            }
            smw[OFF_X0F + i] = __float_as_uint(a);
            smw[OFF_P0  + i] = packh2f(a, b);
            smw[OFF_P0B + i] = packh2f(a, 0.0f);
        }
    }
    __syncthreads();

    // ---- per-thread precomputed bases ----
    const int g = lane >> 2, t = lane & 3;
    const int r = wid;                    // tile row for this warp (0..15)
    const int i2   = OFF_X2P + (4 * r + t) * X2STR + 2 * g;
    const int i1   = OFF_X1P + (2 * r + t) * 18 + g;
    const int u1o  = OFF_X1P + 2 * r * 18 + g + 72 + (t & 1) * 18 + (t >> 1);
    const int s11a = (t < 2) ? (OFF_X1P + (2 * r + 4 + t) * 18 + g + 2)
                             : (OFF_P0  + (r + t - 2) * 18 + g);
    const int s11b = (t == 0) ? (OFF_P0  + (r + 2) * 18 + g)
                              : (OFF_P0B + (r + t - 1) * 18 + g + 2);
    const int wfb  = OFF_WF + 16 * g + 4 * t;

    float acc[8][4];
#pragma unroll
    for (int nb = 0; nb < 8; ++nb)
#pragma unroll
        for (int q = 0; q < 4; ++q) acc[nb][q] = 0.0f;

#pragma unroll
    for (int s = 0; s < 12; ++s) {
        uint32_t a0, a1, a2, a3;
        if (s < 6) {
            // a2/a3 are +4 patch rows = +4*X2STR = +148
            a0 = smw[i2 + s];        a1 = smw[i2 + 16 + s];
            a2 = smw[i2 + 148 + s];  a3 = smw[i2 + 164 + s];
        } else if (s < 9) {
            // +8 patch rows = +8*X2STR = +296
            const int m2 = 2 * (s - 6);
            a0 = smw[i2 + 296 + m2]; a1 = smw[i2 + 312 + m2];
            a2 = smw[i2 + 297 + m2]; a3 = smw[i2 + 313 + m2];
        } else if (s == 9) {
            a0 = smw[i1];     a1 = smw[i1 + 8];
            a2 = smw[i1 + 1]; a3 = smw[i1 + 9];
        } else if (s == 10) {
            a0 = smw[i1 + 2]; a1 = smw[i1 + 10];
            a2 = smw[u1o];    a3 = smw[u1o + 8];
        } else {
            a0 = smw[s11a];   a1 = smw[s11a + 8];
            a2 = smw[s11b];   a3 = smw[s11b + 8];
        }
#pragma unroll
        for (int nbp = 0; nbp < 4; ++nbp) {
            uint4 b = *(const uint4*)(smw + wfb + (s * 4 + nbp) * 132);
            mma_f16(acc[2 * nbp],     a0, a1, a2, a3, b.x, b.y);
            mma_f16(acc[2 * nbp + 1], a0, a1, a2, a3, b.z, b.w);
        }
    }

    // ---- epilogue: positions (r, g) and (r, g+8) ----
    // Logits tiny (|x| < ~1): softmax without max-subtraction is safe;
    // exp(relu(x)) == fmax(exp(x), 1).
#pragma unroll
    for (int rr = 0; rr < 2; ++rr) {
        const int c = g + 8 * rr;
        const float xsel = __uint_as_float(smw[OFF_X0F + (r + 1) * 18 + (c + 1)]);

        float e[16];
#pragma unroll
        for (int nb = 0; nb < 8; ++nb) {
            e[2 * nb]     = fmaxf(__expf(acc[nb][rr * 2]),     1.0f);
            e[2 * nb + 1] = fmaxf(__expf(acc[nb][rr * 2 + 1]), 1.0f);
        }
        float sum[8];
#pragma unroll
        for (int o = 0; o < 8; ++o) sum[o] = e[o] + e[o + 8];
#pragma unroll
        for (int o = 0; o < 4; ++o) sum[o] += sum[o + 4];
        float ssum = (sum[0] + sum[1]) + (sum[2] + sum[3]);
        ssum += __shfl_xor_sync(0xffffffffu, ssum, 1);
        ssum += __shfl_xor_sync(0xffffffffu, ssum, 2);

        const float scale = __fdividef(xsel, ssum);

        const int gi = i0 + r, gj = j0 + c;
        float* base = out + ((size_t)n << 18) + (size_t)(gi * 8) * 512
                          + gj * 8 + 2 * t;
#pragma unroll
        for (int nb = 0; nb < 8; ++nb) {
            float2 o2 = make_float2(scale * e[2 * nb], scale * e[2 * nb + 1]);
            *(float2*)(base + (size_t)nb * 512) = o2;
        }
    }
}

extern "C" void kernel_launch(void* const* d_in, const int* in_sizes, int n_in,
                              void* d_out, int out_size)
{
    const float* x0 = (const float*)d_in[0];
    const float* x1 = (const float*)d_in[1];
    const float* x2 = (const float*)d_in[2];
    const float* w  = (const float*)d_in[3];
    float* out = (float*)d_out;

    wprep<<<6, 256>>>(w);
    dim3 grid(4, 4, 64);   // 1024 CTAs
    sr_f16<<<grid, NT>>>(x0, x1, x2, out);
}